// round 16
// baseline (speedup 1.0000x reference)
#include <cuda_runtime.h>
#include <cuda_fp16.h>
#include <cstdint>

#define H_  8
#define D_  512
#define DK_ 64
#define B_  16
#define N_  8192
#define ROWS_ (B_ * N_)

// ---------------- device scratch ---------------------------------------------
__device__ float g_scores[B_ * H_ * N_];                 // scores -> exp weights
__device__ float g_inv[B_ * H_];
__device__ float g_partial[B_ * H_ * 16 * DK_];
__device__ __half g_wk[D_ * D_];
__device__ __half g_wg[D_ * D_];

// ---------------- helpers ----------------------------------------------------
__device__ __forceinline__ uint32_t smem_u32(const void* p) {
    uint32_t a;
    asm("{ .reg .u64 t; cvta.to.shared.u64 t, %1; cvt.u32.u64 %0, t; }" : "=r"(a) : "l"(p));
    return a;
}
__device__ __forceinline__ uint32_t swz(uint32_t off) { return off ^ ((off >> 3) & 0x70); }

__device__ __forceinline__ void ldsm4(uint32_t* r, uint32_t addr) {
    asm volatile("ldmatrix.sync.aligned.m8n8.x4.shared.b16 {%0,%1,%2,%3}, [%4];"
        : "=r"(r[0]), "=r"(r[1]), "=r"(r[2]), "=r"(r[3]) : "r"(addr));
}
__device__ __forceinline__ void mma16816(float* d, const uint32_t* a, const uint32_t* b) {
    asm volatile("mma.sync.aligned.m16n8k16.row.col.f32.f16.f16.f32 "
        "{%0,%1,%2,%3}, {%4,%5,%6,%7}, {%8,%9}, {%0,%1,%2,%3};"
        : "+f"(d[0]), "+f"(d[1]), "+f"(d[2]), "+f"(d[3])
        : "r"(a[0]), "r"(a[1]), "r"(a[2]), "r"(a[3]), "r"(b[0]), "r"(b[1]));
}
#define CP16(dst, src) asm volatile("cp.async.cg.shared.global [%0], [%1], 16;" :: "r"(dst), "l"(src) : "memory")
#define CP_COMMIT()    asm volatile("cp.async.commit_group;" ::: "memory")
#define CP_WAIT0()     asm volatile("cp.async.wait_group 0;" ::: "memory")

// fused gate: tanh(k) * sigmoid(g) = (e^{2k}-1) / ((e^{2k}+1)(1+e^{-g}))
__device__ __forceinline__ float gatefn(float k, float g) {
    float t  = __expf(2.f * k);
    float eg = __expf(-g);
    return __fdividef(t - 1.f, (t + 1.f) * (1.f + eg));
}

// ---------------- SMEM layout --------------------------------------------
// W stages: 2 x 16KB (wk 8K + wg 8K per stage), double-buffered.
// Xf16: single 16KB buffer (128x64 fp16), guarded by two per-iter barriers.
#define SMW_BASE  0          // + s*16384 + sel*8192
#define SMXF      32768      // 16 KB
#define SM_Q      49152      // 2 KB (512 f32)
#define SM_SPART  51200      // 2 KB (4x128 f32)
#define SMEM_TOTAL 53248     // -> occ 2 with margin

// ---------------------------------------------------------------------------
__global__ void cvt_w_kernel(const float* __restrict__ Wk, const float* __restrict__ Wg)
{
    int i = blockIdx.x * 256 + threadIdx.x;
    g_wk[i] = __float2half(Wk[i]);
    g_wg[i] = __float2half(Wg[i]);
}

// ---------------------------------------------------------------------------
// W stage loader: 2 tiles [64x64] fp16 via cp.async 16B.
// it: head h = it>>3, k-chunk c = it&7.
// ---------------------------------------------------------------------------
__device__ __forceinline__ void load_w(uint32_t sb, int s, int it)
{
    const int tid = threadIdx.x;
    const int h   = it >> 3;
    const int kk  = (it & 7) << 6;
    const uint32_t st = sb + SMW_BASE + (uint32_t)s * 16384;

    const __half* wsrc[2] = { g_wk, g_wg };
#pragma unroll
    for (int a = 0; a < 2; ++a) {
        const __half* src = wsrc[a] + (size_t)(h * DK_) * D_ + kk;
        const uint32_t dst = st + (uint32_t)a * 8192;
#pragma unroll
        for (int i = 0; i < 2; ++i) {
            int idx = i * 256 + tid;        // 0..511 chunks (64 rows x 8)
            int r   = idx >> 3;
            int cc  = idx & 7;
            CP16(dst + swz((uint32_t)(r * 128 + cc * 16)), src + (size_t)r * D_ + cc * 8);
        }
    }
}

// ---------------------------------------------------------------------------
// Pass 1: occ-2 fp16 single-product GEMM, inline X f32->f16 conversion.
// 1024 CTAs x 256 thr (8 warps: 2m x 4n), 64 iterations (8 heads x 8 kc).
// Per iteration: wait W stage -> sync1 -> issue W(it+1) -> LDG/cvt/STS X
//                -> sync2 -> ldsm/MMA -> (epilogue every 8th).
// ---------------------------------------------------------------------------
__global__ __launch_bounds__(256, 2)
void pass1_kernel(const float* __restrict__ x, const float* __restrict__ q)
{
    extern __shared__ char smem[];
    const uint32_t sb = smem_u32(smem);
    const int tid    = threadIdx.x;
    const int lane   = tid & 31;
    const int wid    = tid >> 5;
    const int warp_m = wid & 1;          // 64-row half
    const int warp_n = wid >> 1;         // 0..3 : 16-col group

    const int row0 = blockIdx.x * 128;
    const int b    = row0 >> 13;
    const int n0   = row0 & (N_ - 1);

    for (int i = tid; i < 512; i += 256)
        ((float*)(smem + SM_Q))[i] = q[i];

    const int a_r   = warp_m * 64 + (lane & 15);
    const int a_c16 = lane >> 4;
    const int b_n   = warp_n * 16 + (lane & 7) + ((lane >> 4) << 3);
    const int b_c16 = (lane >> 3) & 1;

    // fixed X chunk coords for this thread (4 chunks of 16B fp16 = 8 cols)
    const int xr[4] = { tid >> 3, (256 + tid) >> 3, (512 + tid) >> 3, (768 + tid) >> 3 };
    const int xc    = tid & 7;

    float* spart = (float*)(smem + SM_SPART);
    const float* qs = (const float*)(smem + SM_Q);

    float aK[4][2][4], aG[4][2][4];

    load_w(sb, 0, 0);
    CP_COMMIT();

    for (int it = 0; it < 64; ++it) {
        const int s = it & 1;
        const int c = it & 7;
        const int h = it >> 3;
        const int kk = c << 6;
        const uint32_t wst = sb + SMW_BASE + (uint32_t)s * 16384;

        if (c == 0) {
#pragma unroll
            for (int mt = 0; mt < 4; ++mt)
#pragma unroll
                for (int nt = 0; nt < 2; ++nt)
#pragma unroll
                    for (int e = 0; e < 4; ++e) { aK[mt][nt][e] = 0.f; aG[mt][nt][e] = 0.f; }
        }

        CP_WAIT0();            // W stage s landed (this thread's groups)
        __syncthreads();       // sync1: W s visible; all ldsm/Xf16 reads of it-1 done

        if (it < 63) {         // issue next W loads; land during MMA block
            load_w(sb, s ^ 1, it + 1);
            CP_COMMIT();
        }

        // ---- inline X convert: LDG f32 -> f16 -> STS (single buffer) ----
#pragma unroll
        for (int i = 0; i < 4; ++i) {
            const float* xp = x + (size_t)(row0 + xr[i]) * D_ + kk + xc * 8;
            float4 v0 = *(const float4*)xp;
            float4 v1 = *(const float4*)(xp + 4);
            __half2 h0 = __floats2half2_rn(v0.x, v0.y);
            __half2 h1 = __floats2half2_rn(v0.z, v0.w);
            __half2 h2 = __floats2half2_rn(v1.x, v1.y);
            __half2 h3 = __floats2half2_rn(v1.z, v1.w);
            uint4 pk;
            pk.x = *(uint32_t*)&h0; pk.y = *(uint32_t*)&h1;
            pk.z = *(uint32_t*)&h2; pk.w = *(uint32_t*)&h3;
            *(uint4*)(smem + SMXF + swz((uint32_t)(xr[i] * 128 + xc * 16))) = pk;
        }
        __syncthreads();       // sync2: Xf16 tile ready

        // ---- MMAs: 4 k-steps of 16, single product ----
#pragma unroll
        for (int ks = 0; ks < 4; ++ks) {
            uint32_t Ah[4][4];
#pragma unroll
            for (int mt = 0; mt < 4; ++mt) {
                uint32_t off = swz((uint32_t)((a_r + mt * 16) * 128 + (a_c16 + ks * 2) * 16));
                ldsm4(Ah[mt], sb + SMXF + off);
            }
#pragma unroll
            for (int sel = 0; sel < 2; ++sel) {
                const uint32_t bw = wst + (uint32_t)sel * 8192;
                uint32_t Bh[4];
                uint32_t off = swz((uint32_t)(b_n * 128 + (b_c16 + ks * 2) * 16));
                ldsm4(Bh, bw + off);
#pragma unroll
                for (int mt = 0; mt < 4; ++mt) {
#pragma unroll
                    for (int nt = 0; nt < 2; ++nt) {
                        float* acc = sel ? aG[mt][nt] : aK[mt][nt];
                        mma16816(acc, Ah[mt], &Bh[nt * 2]);
                    }
                }
            }
        }

        if (c == 7) {
            // ---- epilogue: fused gate + q-dot -> scores for head h ----
            const int cb = warp_n * 16 + 2 * (lane & 3);
#pragma unroll
            for (int mt = 0; mt < 4; ++mt) {
                float p0 = 0.f, p1 = 0.f;
#pragma unroll
                for (int nt = 0; nt < 2; ++nt) {
                    int col = cb + nt * 8;
                    float q0 = qs[h * DK_ + col];
                    float q1 = qs[h * DK_ + col + 1];
                    const float* K = aK[mt][nt];
                    const float* G = aG[mt][nt];
                    p0 += q0 * gatefn(K[0], G[0]);
                    p0 += q1 * gatefn(K[1], G[1]);
                    p1 += q0 * gatefn(K[2], G[2]);
                    p1 += q1 * gatefn(K[3], G[3]);
                }
                p0 += __shfl_xor_sync(0xffffffffu, p0, 1);
                p0 += __shfl_xor_sync(0xffffffffu, p0, 2);
                p1 += __shfl_xor_sync(0xffffffffu, p1, 1);
                p1 += __shfl_xor_sync(0xffffffffu, p1, 2);
                if ((lane & 3) == 0) {
                    int row = warp_m * 64 + mt * 16 + (lane >> 2);
                    spart[warp_n * 128 + row]     = p0;
                    spart[warp_n * 128 + row + 8] = p1;
                }
            }
            __syncthreads();   // spart writes -> reads
            if (tid < 128) {
                float sc = (spart[tid] + spart[128 + tid])
                         + (spart[256 + tid] + spart[384 + tid]);
                g_scores[((size_t)b * H_ + h) * N_ + n0 + tid] = sc;
            }
            // next iteration's sync1 protects spart reuse
        }
    }
}

// ---------------------------------------------------------------------------
__global__ __launch_bounds__(1024)
void pass2a_kernel()
{
    __shared__ float red[32];
    const int bh  = blockIdx.x;
    const int tid = threadIdx.x;
    float* sc = g_scores + (size_t)bh * N_;

    float mx = -1e30f;
    for (int i = tid; i < N_; i += 1024) mx = fmaxf(mx, sc[i]);
#pragma unroll
    for (int off = 16; off >= 1; off >>= 1)
        mx = fmaxf(mx, __shfl_xor_sync(0xffffffffu, mx, off));
    if ((tid & 31) == 0) red[tid >> 5] = mx;
    __syncthreads();
    if (tid < 32) {
        float v = red[tid];
#pragma unroll
        for (int off = 16; off >= 1; off >>= 1)
            v = fmaxf(v, __shfl_xor_sync(0xffffffffu, v, off));
        if (tid == 0) red[0] = v;
    }
    __syncthreads();
    mx = red[0];
    __syncthreads();

    float sum = 0.f;
    for (int i = tid; i < N_; i += 1024) {
        float e = __expf(sc[i] - mx);
        sc[i] = e;
        sum += e;
    }
#pragma unroll
    for (int off = 16; off >= 1; off >>= 1)
        sum += __shfl_xor_sync(0xffffffffu, sum, off);
    if ((tid & 31) == 0) red[tid >> 5] = sum;
    __syncthreads();
    if (tid < 32) {
        float v = red[tid];
#pragma unroll
        for (int off = 16; off >= 1; off >>= 1)
            v += __shfl_xor_sync(0xffffffffu, v, off);
        if (tid == 0) g_inv[bh] = 1.f / v;
    }
}

// grid = 128 bh x 16 chunks of 512 rows
__global__ __launch_bounds__(256)
void pass2b_kernel(const float* __restrict__ x)
{
    __shared__ float red[256];
    const int bh = blockIdx.x >> 4;
    const int ch = blockIdx.x & 15;
    const int b  = bh >> 3;
    const int h  = bh & 7;
    const int tid = threadIdx.x;
    const int d   = tid & 63;
    const int sl  = tid >> 6;

    const float* w  = g_scores + (size_t)bh * N_;
    const float* xp = x + (size_t)b * N_ * D_ + h * DK_ + d;
    const int base = ch * 512;

    float a = 0.f;
    for (int n = base + sl; n < base + 512; n += 16) {
        a = fmaf(w[n],      xp[(size_t)(n)      * D_], a);
        a = fmaf(w[n + 4],  xp[(size_t)(n + 4)  * D_], a);
        a = fmaf(w[n + 8],  xp[(size_t)(n + 8)  * D_], a);
        a = fmaf(w[n + 12], xp[(size_t)(n + 12) * D_], a);
    }
    red[tid] = a;
    __syncthreads();
    if (tid < 64)
        g_partial[((size_t)bh * 16 + ch) * DK_ + tid] =
            (red[tid] + red[tid + 64]) + (red[tid + 128] + red[tid + 192]);
}

__global__ __launch_bounds__(512)
void pass2c_kernel(float* __restrict__ out)
{
    const int b   = blockIdx.x;
    const int col = threadIdx.x;
    const int h   = col >> 6;
    const int d   = col & 63;
    const int bh  = b * 8 + h;
    float s = 0.f;
#pragma unroll
    for (int ch = 0; ch < 16; ++ch)
        s += g_partial[((size_t)bh * 16 + ch) * DK_ + d];
    out[(size_t)b * D_ + col] = s * g_inv[bh];
}

// ---------------------------------------------------------------------------
extern "C" void kernel_launch(void* const* d_in, const int* in_sizes, int n_in,
                              void* d_out, int out_size)
{
    const float* x  = (const float*)d_in[0];
    const float* Wk = (const float*)d_in[1];
    const float* Wg = (const float*)d_in[2];
    const float* q  = (const float*)d_in[3];
    float* out = (float*)d_out;

    cudaFuncSetAttribute(pass1_kernel, cudaFuncAttributeMaxDynamicSharedMemorySize, SMEM_TOTAL);

    cvt_w_kernel<<<1024, 256>>>(Wk, Wg);
    pass1_kernel<<<ROWS_ / 128, 256, SMEM_TOTAL>>>(x, q);
    pass2a_kernel<<<B_ * H_, 1024>>>();
    pass2b_kernel<<<B_ * H_ * 16, 256>>>(x);
    pass2c_kernel<<<B_, 512>>>(out);
}

// round 17
// speedup vs baseline: 1.2426x; 1.2426x over previous
#include <cuda_runtime.h>
#include <cuda_fp16.h>
#include <cstdint>

#define H_  8
#define D_  512
#define DK_ 64
#define B_  16
#define N_  8192
#define ROWS_ (B_ * N_)

// ---------------- device scratch ---------------------------------------------
__device__ float g_scores[B_ * H_ * N_];                 // scores -> exp weights
__device__ float g_inv[B_ * H_];
__device__ float g_partial[B_ * H_ * 16 * DK_];
__device__ __half g_wk[D_ * D_];
__device__ __half g_wg[D_ * D_];
__device__ __half g_xh[(size_t)ROWS_ * D_];              // 128 MB

// ---------------- helpers ----------------------------------------------------
__device__ __forceinline__ uint32_t smem_u32(const void* p) {
    uint32_t a;
    asm("{ .reg .u64 t; cvta.to.shared.u64 t, %1; cvt.u32.u64 %0, t; }" : "=r"(a) : "l"(p));
    return a;
}
__device__ __forceinline__ uint32_t swz(uint32_t off) { return off ^ ((off >> 3) & 0x70); }

__device__ __forceinline__ void ldsm4(uint32_t* r, uint32_t addr) {
    asm volatile("ldmatrix.sync.aligned.m8n8.x4.shared.b16 {%0,%1,%2,%3}, [%4];"
        : "=r"(r[0]), "=r"(r[1]), "=r"(r[2]), "=r"(r[3]) : "r"(addr));
}
__device__ __forceinline__ void mma16816(float* d, const uint32_t* a, const uint32_t* b) {
    asm volatile("mma.sync.aligned.m16n8k16.row.col.f32.f16.f16.f32 "
        "{%0,%1,%2,%3}, {%4,%5,%6,%7}, {%8,%9}, {%0,%1,%2,%3};"
        : "+f"(d[0]), "+f"(d[1]), "+f"(d[2]), "+f"(d[3])
        : "r"(a[0]), "r"(a[1]), "r"(a[2]), "r"(a[3]), "r"(b[0]), "r"(b[1]));
}
#define CP16(dst, src) asm volatile("cp.async.cg.shared.global [%0], [%1], 16;" :: "r"(dst), "l"(src) : "memory")
#define CP_COMMIT()    asm volatile("cp.async.commit_group;" ::: "memory")
#define CP_WAIT0()     asm volatile("cp.async.wait_group 0;" ::: "memory")

// fused gate: tanh(k) * sigmoid(g) = (e^{2k}-1) / ((e^{2k}+1)(1+e^{-g}))
__device__ __forceinline__ float gatefn(float k, float g) {
    float t  = __expf(2.f * k);
    float eg = __expf(-g);
    return __fdividef(t - 1.f, (t + 1.f) * (1.f + eg));
}

// ---------------- SMEM layout: two 32KB stages + q + spart -------------------
// stage: X 16KB (128x64 fp16) | W 2x8KB (64x64 fp16: wk, wg)
#define SM_STAGE  32768
#define SMX       0
#define SMW       16384      // +a*8192
#define SM_Q      (2 * SM_STAGE)          // 65536 (512 f32)
#define SM_SPART  (SM_Q + 2048)           // 67584 (4x128 f32)
#define SMEM_TOTAL (SM_SPART + 2048)      // 69632 -> 2 CTAs/SM

// ---------------------------------------------------------------------------
__global__ void cvt_w_kernel(const float* __restrict__ Wk, const float* __restrict__ Wg)
{
    int i = blockIdx.x * 256 + threadIdx.x;
    g_wk[i] = __float2half(Wk[i]);
    g_wg[i] = __float2half(Wg[i]);
}

__global__ __launch_bounds__(256)
void cvt_x_kernel(const float* __restrict__ x)
{
    size_t i = ((size_t)blockIdx.x * 256 + threadIdx.x) * 4;
    float4 v = *(const float4*)(x + i);
    __half2 p0 = make_half2(__float2half(v.x), __float2half(v.y));
    __half2 p1 = make_half2(__float2half(v.z), __float2half(v.w));
    *(uint2*)(g_xh + i) = make_uint2(*(uint32_t*)&p0, *(uint32_t*)&p1);
}

// ---------------------------------------------------------------------------
// Stage loader: X tile [128x64] + 2 W tiles [64x64] fp16, cp.async 16B.
// it: head h = it>>3, k-chunk c = it&7.
// ---------------------------------------------------------------------------
__device__ __forceinline__ void load_stage(uint32_t sb, int s, int it, int row0)
{
    const int tid = threadIdx.x;
    const int h   = it >> 3;
    const int kk  = (it & 7) << 6;
    const uint32_t st = sb + (uint32_t)s * SM_STAGE;

#pragma unroll
    for (int i = 0; i < 4; ++i) {
        int idx = i * 256 + tid;            // 0..1023 16B chunks
        int r   = idx >> 3;
        int cc  = idx & 7;
        CP16(st + SMX + swz((uint32_t)(r * 128 + cc * 16)),
             g_xh + (size_t)(row0 + r) * D_ + kk + cc * 8);
    }
    const __half* wsrc[2] = { g_wk, g_wg };
#pragma unroll
    for (int a = 0; a < 2; ++a) {
        const __half* src = wsrc[a] + (size_t)(h * DK_) * D_ + kk;
        const uint32_t dst = st + SMW + (uint32_t)a * 8192;
#pragma unroll
        for (int i = 0; i < 2; ++i) {
            int idx = i * 256 + tid;        // 0..511 chunks (64 rows x 8)
            int r   = idx >> 3;
            int cc  = idx & 7;
            CP16(dst + swz((uint32_t)(r * 128 + cc * 16)), src + (size_t)r * D_ + cc * 8);
        }
    }
}

// ---------------------------------------------------------------------------
// Pass 1: occ-2 cp.async double-buffered fp16 single-product GEMM + gate+q-dot.
// 1024 CTAs x 256 thr (8 warps: 2m x 4n), 64 iterations (8 heads x 8 kc).
// Per iteration: one head (N=64), warp covers 64 rows x 16 cols.
// ---------------------------------------------------------------------------
__global__ __launch_bounds__(256, 2)
void pass1_kernel(const float* __restrict__ q)
{
    extern __shared__ char smem[];
    const uint32_t sb = smem_u32(smem);
    const int tid    = threadIdx.x;
    const int lane   = tid & 31;
    const int wid    = tid >> 5;
    const int warp_m = wid & 1;          // 64-row half
    const int warp_n = wid >> 1;         // 0..3 : 16-col group

    const int row0 = blockIdx.x * 128;
    const int b    = row0 >> 13;
    const int n0   = row0 & (N_ - 1);

    for (int i = tid; i < 512; i += 256)
        ((float*)(smem + SM_Q))[i] = q[i];

    const int a_r   = warp_m * 64 + (lane & 15);
    const int a_c16 = lane >> 4;
    const int b_n   = warp_n * 16 + (lane & 7) + ((lane >> 4) << 3);
    const int b_c16 = (lane >> 3) & 1;

    float* spart = (float*)(smem + SM_SPART);
    const float* qs = (const float*)(smem + SM_Q);

    float aK[4][2][4], aG[4][2][4];

    load_stage(sb, 0, 0, row0);
    CP_COMMIT();

    for (int it = 0; it < 64; ++it) {
        const int s = it & 1;
        const int c = it & 7;
        const int h = it >> 3;
        const uint32_t st = sb + (uint32_t)s * SM_STAGE;

        if (c == 0) {
#pragma unroll
            for (int mt = 0; mt < 4; ++mt)
#pragma unroll
                for (int nt = 0; nt < 2; ++nt)
#pragma unroll
                    for (int e = 0; e < 4; ++e) { aK[mt][nt][e] = 0.f; aG[mt][nt][e] = 0.f; }
        }

        CP_WAIT0();            // stage s loads (this thread) complete
        __syncthreads();       // all loads visible; stage s^1 reads done

        if (it < 63) {         // issue next loads; land during MMA block
            load_stage(sb, s ^ 1, it + 1, row0);
            CP_COMMIT();
        }

        // ---- MMAs: 4 k-steps of 16, single product ----
#pragma unroll
        for (int ks = 0; ks < 4; ++ks) {
            uint32_t Ah[4][4];
#pragma unroll
            for (int mt = 0; mt < 4; ++mt) {
                uint32_t off = swz((uint32_t)((a_r + mt * 16) * 128 + (a_c16 + ks * 2) * 16));
                ldsm4(Ah[mt], st + SMX + off);
            }
#pragma unroll
            for (int sel = 0; sel < 2; ++sel) {
                const uint32_t bw = st + SMW + (uint32_t)sel * 8192;
                uint32_t Bh[4];
                uint32_t off = swz((uint32_t)(b_n * 128 + (b_c16 + ks * 2) * 16));
                ldsm4(Bh, bw + off);
#pragma unroll
                for (int mt = 0; mt < 4; ++mt) {
#pragma unroll
                    for (int nt = 0; nt < 2; ++nt) {
                        float* acc = sel ? aG[mt][nt] : aK[mt][nt];
                        mma16816(acc, Ah[mt], &Bh[nt * 2]);
                    }
                }
            }
        }

        if (c == 7) {
            // ---- epilogue: fused gate + q-dot -> scores for head h ----
            const int cb = warp_n * 16 + 2 * (lane & 3);
#pragma unroll
            for (int mt = 0; mt < 4; ++mt) {
                float p0 = 0.f, p1 = 0.f;
#pragma unroll
                for (int nt = 0; nt < 2; ++nt) {
                    int col = cb + nt * 8;
                    float q0 = qs[h * DK_ + col];
                    float q1 = qs[h * DK_ + col + 1];
                    const float* K = aK[mt][nt];
                    const float* G = aG[mt][nt];
                    p0 += q0 * gatefn(K[0], G[0]);
                    p0 += q1 * gatefn(K[1], G[1]);
                    p1 += q0 * gatefn(K[2], G[2]);
                    p1 += q1 * gatefn(K[3], G[3]);
                }
                p0 += __shfl_xor_sync(0xffffffffu, p0, 1);
                p0 += __shfl_xor_sync(0xffffffffu, p0, 2);
                p1 += __shfl_xor_sync(0xffffffffu, p1, 1);
                p1 += __shfl_xor_sync(0xffffffffu, p1, 2);
                if ((lane & 3) == 0) {
                    int row = warp_m * 64 + mt * 16 + (lane >> 2);
                    spart[warp_n * 128 + row]     = p0;
                    spart[warp_n * 128 + row + 8] = p1;
                }
            }
            __syncthreads();   // spart writes -> reads
            if (tid < 128) {
                float sc = (spart[tid] + spart[128 + tid])
                         + (spart[256 + tid] + spart[384 + tid]);
                g_scores[((size_t)b * H_ + h) * N_ + n0 + tid] = sc;
            }
            // next iteration's top barrier protects spart reuse
        }
    }
}

// ---------------------------------------------------------------------------
__global__ __launch_bounds__(1024)
void pass2a_kernel()
{
    __shared__ float red[32];
    const int bh  = blockIdx.x;
    const int tid = threadIdx.x;
    float* sc = g_scores + (size_t)bh * N_;

    float mx = -1e30f;
    for (int i = tid; i < N_; i += 1024) mx = fmaxf(mx, sc[i]);
#pragma unroll
    for (int off = 16; off >= 1; off >>= 1)
        mx = fmaxf(mx, __shfl_xor_sync(0xffffffffu, mx, off));
    if ((tid & 31) == 0) red[tid >> 5] = mx;
    __syncthreads();
    if (tid < 32) {
        float v = red[tid];
#pragma unroll
        for (int off = 16; off >= 1; off >>= 1)
            v = fmaxf(v, __shfl_xor_sync(0xffffffffu, v, off));
        if (tid == 0) red[0] = v;
    }
    __syncthreads();
    mx = red[0];
    __syncthreads();

    float sum = 0.f;
    for (int i = tid; i < N_; i += 1024) {
        float e = __expf(sc[i] - mx);
        sc[i] = e;
        sum += e;
    }
#pragma unroll
    for (int off = 16; off >= 1; off >>= 1)
        sum += __shfl_xor_sync(0xffffffffu, sum, off);
    if ((tid & 31) == 0) red[tid >> 5] = sum;
    __syncthreads();
    if (tid < 32) {
        float v = red[tid];
#pragma unroll
        for (int off = 16; off >= 1; off >>= 1)
            v += __shfl_xor_sync(0xffffffffu, v, off);
        if (tid == 0) g_inv[bh] = 1.f / v;
    }
}

// grid = 128 bh x 16 chunks of 512 rows; reads fp16 X (half the traffic)
__global__ __launch_bounds__(256)
void pass2b_kernel()
{
    __shared__ float red[256];
    const int bh = blockIdx.x >> 4;
    const int ch = blockIdx.x & 15;
    const int b  = bh >> 3;
    const int h  = bh & 7;
    const int tid = threadIdx.x;
    const int d   = tid & 63;
    const int sl  = tid >> 6;

    const float* w   = g_scores + (size_t)bh * N_;
    const __half* xp = g_xh + (size_t)b * N_ * D_ + h * DK_ + d;
    const int base = ch * 512;

    float a = 0.f;
    for (int n = base + sl; n < base + 512; n += 16) {
        a = fmaf(w[n],      __half2float(xp[(size_t)(n)      * D_]), a);
        a = fmaf(w[n + 4],  __half2float(xp[(size_t)(n + 4)  * D_]), a);
        a = fmaf(w[n + 8],  __half2float(xp[(size_t)(n + 8)  * D_]), a);
        a = fmaf(w[n + 12], __half2float(xp[(size_t)(n + 12) * D_]), a);
    }
    red[tid] = a;
    __syncthreads();
    if (tid < 64)
        g_partial[((size_t)bh * 16 + ch) * DK_ + tid] =
            (red[tid] + red[tid + 64]) + (red[tid + 128] + red[tid + 192]);
}

__global__ __launch_bounds__(512)
void pass2c_kernel(float* __restrict__ out)
{
    const int b   = blockIdx.x;
    const int col = threadIdx.x;
    const int h   = col >> 6;
    const int d   = col & 63;
    const int bh  = b * 8 + h;
    float s = 0.f;
#pragma unroll
    for (int ch = 0; ch < 16; ++ch)
        s += g_partial[((size_t)bh * 16 + ch) * DK_ + d];
    out[(size_t)b * D_ + col] = s * g_inv[bh];
}

// ---------------------------------------------------------------------------
extern "C" void kernel_launch(void* const* d_in, const int* in_sizes, int n_in,
                              void* d_out, int out_size)
{
    const float* x  = (const float*)d_in[0];
    const float* Wk = (const float*)d_in[1];
    const float* Wg = (const float*)d_in[2];
    const float* q  = (const float*)d_in[3];
    float* out = (float*)d_out;

    cudaFuncSetAttribute(pass1_kernel, cudaFuncAttributeMaxDynamicSharedMemorySize, SMEM_TOTAL);

    cvt_w_kernel<<<1024, 256>>>(Wk, Wg);
    cvt_x_kernel<<<(int)((size_t)ROWS_ * D_ / 1024), 256>>>(x);
    pass1_kernel<<<ROWS_ / 128, 256, SMEM_TOTAL>>>(q);
    pass2a_kernel<<<B_ * H_, 1024>>>();
    pass2b_kernel<<<B_ * H_ * 16, 256>>>();
    pass2c_kernel<<<B_, 512>>>(out);
}